// round 3
// baseline (speedup 1.0000x reference)
#include <cuda_runtime.h>
#include <cstdint>

// Problem constants (B,H,W,D = 32,32,32,64; K = 1024)
#define N_ROWS 32768
#define DIM    64
#define KCODES 1024
#define RB     128    // rows per block tile
#define CBT    128    // codes per block tile
#define NTHREADS 256  // 16x16 thread tile, each thread 8 rows x 8 codes

// Scratch (device globals -- no allocation allowed)
__device__ unsigned long long g_rowbest[N_ROWS];   // (dist_bits<<32)|code
__device__ unsigned int       g_colmin[KCODES];    // per-code min dist (float bits)
__device__ float              g_xnorm[N_ROWS];
__device__ float              g_cnorm[KCODES];
__device__ float              g_partials[N_ROWS / 256];

// Shared memory layout (dynamic):
//   xs2: 64 rowpairs x 65 u64  (f32x2: even row in lo, odd row in hi)
//   cs2: 128 codes   x 65 u64  (value duplicated in both halves)
//   colred: 128 u32
#define XS2_U64   (64 * 65)
#define CS2_U64   (128 * 65)
#define SMEM_BYTES ((XS2_U64 + CS2_U64) * 8 + CBT * 4)

__device__ __forceinline__ void unpack2(unsigned long long v, float& lo, float& hi) {
    asm("mov.b64 {%0,%1}, %2;" : "=f"(lo), "=f"(hi) : "l"(v));
}
__device__ __forceinline__ void fma2(unsigned long long& acc,
                                     unsigned long long a, unsigned long long b) {
    asm("fma.rn.f32x2 %0, %1, %2, %0;" : "+l"(acc) : "l"(a), "l"(b));
}
__device__ __forceinline__ unsigned long long u64min(unsigned long long a,
                                                     unsigned long long b) {
    return (b < a) ? b : a;
}

// ---------------------------------------------------------------------------
// Kernel 1: init scratch + precompute ||x||^2 per row and ||c||^2 per code
// ---------------------------------------------------------------------------
__global__ void vq_prep(const float* __restrict__ x, const float* __restrict__ cb) {
    int t = blockIdx.x * blockDim.x + threadIdx.x;
    if (t < N_ROWS) {
        const float4* p = reinterpret_cast<const float4*>(x) + (size_t)t * (DIM / 4);
        float s = 0.f;
#pragma unroll
        for (int i = 0; i < DIM / 4; i++) {
            float4 v = p[i];
            s += v.x * v.x + v.y * v.y + v.z * v.z + v.w * v.w;
        }
        g_xnorm[t] = s;
        g_rowbest[t] = 0xFFFFFFFFFFFFFFFFull;
    }
    if (t < KCODES) {
        const float4* p = reinterpret_cast<const float4*>(cb) + (size_t)t * (DIM / 4);
        float s = 0.f;
#pragma unroll
        for (int i = 0; i < DIM / 4; i++) {
            float4 v = p[i];
            s += v.x * v.x + v.y * v.y + v.z * v.z + v.w * v.w;
        }
        g_cnorm[t] = s;
        g_colmin[t] = 0x7F800000u;  // +inf bits
    }
}

// ---------------------------------------------------------------------------
// Kernel 2: distance GEMM tile + row argmin (u64 atomicMin) + column min
// ---------------------------------------------------------------------------
__global__ void __launch_bounds__(NTHREADS)
vq_main(const float* __restrict__ x, const float* __restrict__ cb) {
    extern __shared__ unsigned long long smem_u64[];
    unsigned long long* xs2 = smem_u64;            // [rp*65 + d]
    unsigned long long* cs2 = smem_u64 + XS2_U64;  // [c*65 + d]
    unsigned int* colred = (unsigned int*)(smem_u64 + XS2_U64 + CS2_U64);

    const int tid = threadIdx.x;
    const int tx = tid & 15;   // code group
    const int ty = tid >> 4;   // row group
    const int row0 = blockIdx.x * RB;
    const int c0 = blockIdx.y * CBT;

    float* xsf = (float*)xs2;  // rowpair stride 130 floats
    float* csf = (float*)cs2;

    // Load x tile: 128 rows x 16 float4, store as f32x2 row-pairs
    const float4* xg = reinterpret_cast<const float4*>(x);
#pragma unroll
    for (int i = 0; i < 8; i++) {
        int f = tid + i * NTHREADS;      // 0..2047
        int r = f >> 4;                  // local row 0..127
        int d4 = f & 15;
        float4 v = xg[(size_t)(row0 + r) * 16 + d4];
        int rp = r >> 1, half = r & 1;
        int base = rp * 130 + 8 * d4 + half;
        xsf[base + 0] = v.x;
        xsf[base + 2] = v.y;
        xsf[base + 4] = v.z;
        xsf[base + 6] = v.w;
    }
    // Load codebook tile: 128 codes x 16 float4, duplicated halves
    const float4* cg = reinterpret_cast<const float4*>(cb);
#pragma unroll
    for (int i = 0; i < 8; i++) {
        int f = tid + i * NTHREADS;
        int c = f >> 4;
        int d4 = f & 15;
        float4 v = cg[(size_t)(c0 + c) * 16 + d4];
        int base = c * 130 + 8 * d4;
        csf[base + 0] = v.x; csf[base + 1] = v.x;
        csf[base + 2] = v.y; csf[base + 3] = v.y;
        csf[base + 4] = v.z; csf[base + 5] = v.z;
        csf[base + 6] = v.w; csf[base + 7] = v.w;
    }
    if (tid < CBT) colred[tid] = 0x7F800000u;
    __syncthreads();

    // Main loop: acc[p][j] = f32x2 dot of rowpair (ty*8+2p, +1) with code tx+16j
    unsigned long long acc[4][8];
#pragma unroll
    for (int p = 0; p < 4; p++)
#pragma unroll
        for (int j = 0; j < 8; j++) acc[p][j] = 0ull;

    const unsigned long long* xrow = xs2 + (ty * 4) * 65;
    const unsigned long long* crow = cs2 + tx * 65;

#pragma unroll 4
    for (int d = 0; d < DIM; d++) {
        unsigned long long xp0 = xrow[d];
        unsigned long long xp1 = xrow[65 + d];
        unsigned long long xp2 = xrow[130 + d];
        unsigned long long xp3 = xrow[195 + d];
#pragma unroll
        for (int j = 0; j < 8; j++) {
            unsigned long long cp = crow[j * (16 * 65) + d];
            fma2(acc[0][j], xp0, cp);
            fma2(acc[1][j], xp1, cp);
            fma2(acc[2][j], xp2, cp);
            fma2(acc[3][j], xp3, cp);
        }
    }

    // Epilogue: dist = ||x||^2 - 2*dot + ||c||^2
    const int grow0 = row0 + ty * 8;
    float xn[8];
#pragma unroll
    for (int i = 0; i < 8; i++) xn[i] = g_xnorm[grow0 + i];

    const float INF = __int_as_float(0x7f800000);
    float bestd[8];
    int bestc[8];
#pragma unroll
    for (int i = 0; i < 8; i++) { bestd[i] = INF; bestc[i] = 0; }

#pragma unroll
    for (int j = 0; j < 8; j++) {
        int code = tx + 16 * j;              // local code, ascending in j
        float cnj = g_cnorm[c0 + code];
        float colm = INF;
#pragma unroll
        for (int p = 0; p < 4; p++) {
            float lo, hi;
            unpack2(acc[p][j], lo, hi);
            float d0 = fmaf(-2.f, lo, xn[2 * p] + cnj);
            float d1 = fmaf(-2.f, hi, xn[2 * p + 1] + cnj);
            if (d0 < bestd[2 * p]) { bestd[2 * p] = d0; bestc[2 * p] = code; }
            if (d1 < bestd[2 * p + 1]) { bestd[2 * p + 1] = d1; bestc[2 * p + 1] = code; }
            colm = fminf(colm, fminf(d0, d1));
        }
        atomicMin(&colred[code], __float_as_uint(colm));
    }

    // Row argmin across tx (16 lanes per half-warp), then global atomicMin
#pragma unroll
    for (int i = 0; i < 8; i++) {
        unsigned long long u =
            ((unsigned long long)__float_as_uint(bestd[i]) << 32) |
            (unsigned int)(c0 + bestc[i]);
#pragma unroll
        for (int off = 8; off; off >>= 1) {
            unsigned long long o = __shfl_xor_sync(0xFFFFFFFFu, u, off);
            u = u64min(u, o);
        }
        if (tx == 0) atomicMin(&g_rowbest[grow0 + i], u);
    }

    __syncthreads();
    if (tid < CBT) atomicMin(&g_colmin[c0 + tid], colred[tid]);
}

// ---------------------------------------------------------------------------
// Kernel 3: gather emb, write out = x + (emb - x), partial SSE per block
// ---------------------------------------------------------------------------
__global__ void vq_gather(const float* __restrict__ x, const float* __restrict__ cb,
                          float* __restrict__ out) {
    int row = blockIdx.x * blockDim.x + threadIdx.x;
    int tok = (int)(unsigned int)(g_rowbest[row] & 0xFFFFFFFFull);
    const float4* xg = reinterpret_cast<const float4*>(x) + (size_t)row * 16;
    const float4* cg = reinterpret_cast<const float4*>(cb) + (size_t)tok * 16;
    float4* og = reinterpret_cast<float4*>(out) + (size_t)row * 16;
    float s = 0.f;
#pragma unroll
    for (int i = 0; i < 16; i++) {
        float4 xv = xg[i];
        float4 e = cg[i];
        float dx = e.x - xv.x, dy = e.y - xv.y, dz = e.z - xv.z, dw = e.w - xv.w;
        s += dx * dx + dy * dy + dz * dz + dw * dw;
        // straight-through forward value, computed like the reference
        og[i] = make_float4(xv.x + dx, xv.y + dy, xv.z + dz, xv.w + dw);
    }
    // deterministic block reduce
#pragma unroll
    for (int off = 16; off; off >>= 1) s += __shfl_xor_sync(0xFFFFFFFFu, s, off);
    __shared__ float red[8];
    int lane = threadIdx.x & 31, wid = threadIdx.x >> 5;
    if (lane == 0) red[wid] = s;
    __syncthreads();
    if (threadIdx.x == 0) {
        float t = 0.f;
#pragma unroll
        for (int i = 0; i < 8; i++) t += red[i];
        g_partials[blockIdx.x] = t;
    }
}

// ---------------------------------------------------------------------------
// Kernel 4: finalize loss scalar
// ---------------------------------------------------------------------------
__global__ void vq_final(float* __restrict__ out, int nd, int out_size) {
    int t = threadIdx.x;  // 256 threads
    float s = (t < (N_ROWS / 256)) ? g_partials[t] : 0.f;
    float cm = 0.f;
#pragma unroll
    for (int i = 0; i < KCODES / 256; i++)
        cm += __uint_as_float(g_colmin[t + i * 256]);
#pragma unroll
    for (int off = 16; off; off >>= 1) {
        s += __shfl_xor_sync(0xFFFFFFFFu, s, off);
        cm += __shfl_xor_sync(0xFFFFFFFFu, cm, off);
    }
    __shared__ float sh_s[8], sh_c[8];
    int lane = t & 31, wid = t >> 5;
    if (lane == 0) { sh_s[wid] = s; sh_c[wid] = cm; }
    __syncthreads();
    if (t == 0) {
        float st = 0.f, ct = 0.f;
#pragma unroll
        for (int i = 0; i < 8; i++) { st += sh_s[i]; ct += sh_c[i]; }
        // (EMB_W + COMMIT_W) * mse + ENT_W * mean(colmin)
        float loss = 1.25f * (st / (float)nd) + 0.1f * (ct * (1.f / (float)KCODES));
        for (int i = nd; i < out_size; i++) out[i] = loss;
    }
}

// ---------------------------------------------------------------------------
extern "C" void kernel_launch(void* const* d_in, const int* in_sizes, int n_in,
                              void* d_out, int out_size) {
    const float* x = (const float*)d_in[0];   // [32,32,32,64] fp32
    const float* cb = (const float*)d_in[1];  // [1024,64] fp32
    float* out = (float*)d_out;
    int nd = in_sizes[0];  // 2097152

    cudaFuncSetAttribute(vq_main, cudaFuncAttributeMaxDynamicSharedMemorySize,
                         SMEM_BYTES);

    vq_prep<<<64, 512>>>(x, cb);
    dim3 grid(N_ROWS / RB, KCODES / CBT);
    vq_main<<<grid, NTHREADS, SMEM_BYTES>>>(x, cb);
    vq_gather<<<N_ROWS / 256, 256>>>(x, cb, out);
    vq_final<<<1, 256>>>(out, nd, out_size);
}

// round 9
// speedup vs baseline: 1.5960x; 1.5960x over previous
#include <cuda_runtime.h>
#include <cuda_fp16.h>
#include <cstdint>

// Problem constants (B,H,W,D = 32,32,32,64; K = 1024)
#define N_ROWS 32768
#define DIM    64
#define KCODES 1024
#define M_TILE 128
#define N_TILE 128
#define KAUG   192              // 3 chunks x 64 (fp16 2-level split, 3 product terms)
#define KSTEPS (KAUG / 16)      // 12

// ---------------------------------------------------------------------------
// Device scratch (no allocation allowed)
// ---------------------------------------------------------------------------
__device__ unsigned long long g_rowbest[N_ROWS];   // (dist_bits<<32)|code
__device__ unsigned int       g_colmin[KCODES];    // per-code min dist (float bits)
__device__ float              g_xnorm[N_ROWS];
__device__ float              g_cnorm[KCODES];
__device__ float              g_partials[N_ROWS / 256];
__device__ __align__(16) __half g_xaug[(size_t)N_ROWS * KAUG];  // 12.6 MB
__device__ __align__(16) __half g_caug[(size_t)KCODES * KAUG];  // 384 KB

// ---------------------------------------------------------------------------
// SMEM layout (dynamic). Padded K-stride: 192 halfs -> 200 halfs = 400 B
// (rows land on distinct 4-bank groups => conflict-free ldmatrix).
// ---------------------------------------------------------------------------
#define ROWB      400
#define SO_CN     0                        // 128 floats
#define SO_XN     512                      // 128 floats
#define SO_ROWRED 1024                     // 128 u64
#define SO_COLRED 2048                     // 128 u32
#define SO_A      2560                     // 128 * 400 B = 51200
#define SO_B      (SO_A + M_TILE * ROWB)   // 53760
#define SMEM_SZ   (SO_B + N_TILE * ROWB)   // 104960 B

__device__ __forceinline__ uint32_t smem_to_u32(const void* p) {
    uint32_t a;
    asm("{ .reg .u64 t; cvta.to.shared.u64 t, %1; cvt.u32.u64 %0, t; }"
        : "=r"(a) : "l"(p));
    return a;
}

#define LDSM_X4(r0, r1, r2, r3, addr) \
    asm volatile("ldmatrix.sync.aligned.m8n8.x4.shared.b16 {%0,%1,%2,%3}, [%4];" \
                 : "=r"(r0), "=r"(r1), "=r"(r2), "=r"(r3) : "r"(addr))

#define MMA16816(c, a0, a1, a2, a3, b0, b1) \
    asm volatile( \
        "mma.sync.aligned.m16n8k16.row.col.f32.f16.f16.f32 " \
        "{%0,%1,%2,%3}, {%4,%5,%6,%7}, {%8,%9}, {%0,%1,%2,%3};" \
        : "+f"((c)[0]), "+f"((c)[1]), "+f"((c)[2]), "+f"((c)[3]) \
        : "r"(a0), "r"(a1), "r"(a2), "r"(a3), "r"(b0), "r"(b1))

// ---------------------------------------------------------------------------
// Kernel 1: norms + global scratch init
// ---------------------------------------------------------------------------
__global__ void vq_prep(const float* __restrict__ x, const float* __restrict__ cb) {
    int t = blockIdx.x * blockDim.x + threadIdx.x;
    if (t < N_ROWS) {
        const float4* p = reinterpret_cast<const float4*>(x) + (size_t)t * (DIM / 4);
        float s = 0.f;
#pragma unroll
        for (int i = 0; i < DIM / 4; i++) {
            float4 v = p[i];
            s += v.x * v.x + v.y * v.y + v.z * v.z + v.w * v.w;
        }
        g_xnorm[t] = s;
        g_rowbest[t] = 0xFFFFFFFFFFFFFFFFull;
    }
    if (t < KCODES) {
        const float4* p = reinterpret_cast<const float4*>(cb) + (size_t)t * (DIM / 4);
        float s = 0.f;
#pragma unroll
        for (int i = 0; i < DIM / 4; i++) {
            float4 v = p[i];
            s += v.x * v.x + v.y * v.y + v.z * v.z + v.w * v.w;
        }
        g_cnorm[t] = s;
        g_colmin[t] = 0x7F800000u;
    }
}

// ---------------------------------------------------------------------------
// fp16 2-level split, 3 product terms:
//   X chunks: [hi, hi, mid]   C chunks: [hi, mid, hi]
//   sum = hi_x*hi_c + hi_x*mid_c + mid_x*hi_c  (drop mid*mid ~ 2^-22)
// ---------------------------------------------------------------------------
__device__ __forceinline__ void split2h(float v, __half& h, __half& m) {
    h = __float2half_rn(v);
    m = __float2half_rn(v - __half2float(h));
}
__device__ __forceinline__ uint32_t hpack(__half a, __half b) {
    __half2 t = __halves2half2(a, b);
    return *reinterpret_cast<uint32_t*>(&t);
}

__global__ void vq_split_x(const float* __restrict__ x) {
    int t = blockIdx.x * blockDim.x + threadIdx.x;  // 524288 = 32768*16
    int row = t >> 4, q = t & 15;
    float4 v = reinterpret_cast<const float4*>(x)[t];
    __half h[4], m[4];
    split2h(v.x, h[0], m[0]);
    split2h(v.y, h[1], m[1]);
    split2h(v.z, h[2], m[2]);
    split2h(v.w, h[3], m[3]);
    uint2 hh = make_uint2(hpack(h[0], h[1]), hpack(h[2], h[3]));
    uint2 mm = make_uint2(hpack(m[0], m[1]), hpack(m[2], m[3]));
    size_t base = (size_t)row * KAUG + q * 4;
    *reinterpret_cast<uint2*>(&g_xaug[base + 0 * 64]) = hh;
    *reinterpret_cast<uint2*>(&g_xaug[base + 1 * 64]) = hh;
    *reinterpret_cast<uint2*>(&g_xaug[base + 2 * 64]) = mm;
}

__global__ void vq_split_c(const float* __restrict__ cb) {
    int t = blockIdx.x * blockDim.x + threadIdx.x;  // 16384 = 1024*16
    int row = t >> 4, q = t & 15;
    float4 v = reinterpret_cast<const float4*>(cb)[t];
    __half h[4], m[4];
    split2h(v.x, h[0], m[0]);
    split2h(v.y, h[1], m[1]);
    split2h(v.z, h[2], m[2]);
    split2h(v.w, h[3], m[3]);
    uint2 hh = make_uint2(hpack(h[0], h[1]), hpack(h[2], h[3]));
    uint2 mm = make_uint2(hpack(m[0], m[1]), hpack(m[2], m[3]));
    size_t base = (size_t)row * KAUG + q * 4;
    *reinterpret_cast<uint2*>(&g_caug[base + 0 * 64]) = hh;
    *reinterpret_cast<uint2*>(&g_caug[base + 1 * 64]) = mm;
    *reinterpret_cast<uint2*>(&g_caug[base + 2 * 64]) = hh;
}

// ---------------------------------------------------------------------------
// Kernel 2: mma.sync HMMA GEMM tile (128x128, K=192) + argmin/colmin epilogue
// 8 warps in a 2x4 grid; warp tile 64x32; full-K SMEM staging.
// ---------------------------------------------------------------------------
__global__ void __launch_bounds__(256, 2) vq_main_mma() {
    extern __shared__ char smem[];
    uint32_t sb = smem_to_u32(smem);
    float* cn_s = reinterpret_cast<float*>(smem + SO_CN);
    float* xn_s = reinterpret_cast<float*>(smem + SO_XN);
    unsigned long long* rowred =
        reinterpret_cast<unsigned long long*>(smem + SO_ROWRED);
    unsigned int* colred = reinterpret_cast<unsigned int*>(smem + SO_COLRED);

    const int tid = threadIdx.x;
    const int wid = tid >> 5, lane = tid & 31;
    const int wm = wid & 1;       // m block of 64
    const int wn = wid >> 1;      // n block of 32
    const int m0 = blockIdx.x * M_TILE;
    const int c0 = blockIdx.y * N_TILE;

    if (tid < 128) {
        cn_s[tid] = g_cnorm[c0 + tid];
        xn_s[tid] = g_xnorm[m0 + tid];
        rowred[tid] = 0xFFFFFFFFFFFFFFFFull;
        colred[tid] = 0x7F800000u;
    }

    // Stage A (128 x 192 halfs) and B (128 x 192 halfs), padded rows.
    const uint4* xa = reinterpret_cast<const uint4*>(g_xaug);  // 24 uint4 / row
    const uint4* ca = reinterpret_cast<const uint4*>(g_caug);
#pragma unroll
    for (int i = 0; i < 12; i++) {
        int idx = tid + i * 256;            // 0..3071
        int r = idx / 24, q = idx - r * 24;
        uint4 va = xa[(size_t)(m0 + r) * 24 + q];
        *reinterpret_cast<uint4*>(smem + SO_A + r * ROWB + q * 16) = va;
        uint4 vb = ca[(size_t)(c0 + r) * 24 + q];
        *reinterpret_cast<uint4*>(smem + SO_B + r * ROWB + q * 16) = vb;
    }
    __syncthreads();

    // ldmatrix base addresses
    // A x4: lanes 0-15 -> rows (lane&15) @k0, lanes 16-31 -> same rows @k+8
    uint32_t a_base = sb + SO_A + (wm * 64 + (lane & 15)) * ROWB + (lane >> 4) * 16;
    // B x4 (two n-subtiles): group g = lane>>3:
    //   g0: n0-7 @k0, g1: n0-7 @k8, g2: n8-15 @k0, g3: n8-15 @k8
    const int bg = lane >> 3;
    const int bn = ((bg >> 1) << 3) + (lane & 7);   // 0..15 within 16-n pair
    const int bk = (bg & 1) * 16;                   // byte offset (8 halfs)
    uint32_t b_base0 = sb + SO_B + (wn * 32 + 0 + bn) * ROWB + bk;
    uint32_t b_base1 = sb + SO_B + (wn * 32 + 16 + bn) * ROWB + bk;

    float acc[4][4][4];
#pragma unroll
    for (int mi = 0; mi < 4; mi++)
#pragma unroll
        for (int ni = 0; ni < 4; ni++)
#pragma unroll
            for (int j = 0; j < 4; j++) acc[mi][ni][j] = 0.f;

#pragma unroll
    for (int ks = 0; ks < KSTEPS; ks++) {
        uint32_t a[4][4];
#pragma unroll
        for (int mi = 0; mi < 4; mi++)
            LDSM_X4(a[mi][0], a[mi][1], a[mi][2], a[mi][3],
                    a_base + mi * 16 * ROWB + ks * 32);
        uint32_t b[2][4];
        LDSM_X4(b[0][0], b[0][1], b[0][2], b[0][3], b_base0 + ks * 32);
        LDSM_X4(b[1][0], b[1][1], b[1][2], b[1][3], b_base1 + ks * 32);
#pragma unroll
        for (int mi = 0; mi < 4; mi++) {
#pragma unroll
            for (int ni = 0; ni < 4; ni++) {
                const int p = ni >> 1, o = (ni & 1) * 2;
                MMA16816(acc[mi][ni], a[mi][0], a[mi][1], a[mi][2], a[mi][3],
                         b[p][o], b[p][o + 1]);
            }
        }
    }

    // ---------------- Epilogue ----------------
    const int qr = lane >> 2, qc = lane & 3;
    const float INF = __int_as_float(0x7f800000);
    float cmin[4][2];
#pragma unroll
    for (int ni = 0; ni < 4; ni++) { cmin[ni][0] = INF; cmin[ni][1] = INF; }

#pragma unroll
    for (int mi = 0; mi < 4; mi++) {
#pragma unroll
        for (int h = 0; h < 2; h++) {
            int row_l = wm * 64 + mi * 16 + qr + 8 * h;
            float xn = xn_s[row_l];
            float bd = INF;
            int bc = 0;
#pragma unroll
            for (int ni = 0; ni < 4; ni++) {
#pragma unroll
                for (int c = 0; c < 2; c++) {
                    int col_l = wn * 32 + ni * 8 + 2 * qc + c;
                    float d = fmaf(-2.f, acc[mi][ni][2 * h + c], xn + cn_s[col_l]);
                    if (d < bd) { bd = d; bc = col_l; }
                    cmin[ni][c] = fminf(cmin[ni][c], d);
                }
            }
            unsigned long long u =
                ((unsigned long long)__float_as_uint(bd) << 32) |
                (unsigned int)(c0 + bc);
#pragma unroll
            for (int off = 1; off <= 2; off <<= 1) {
                unsigned long long o = __shfl_xor_sync(0xFFFFFFFFu, u, off);
                if (o < u) u = o;
            }
            if (qc == 0) atomicMin(&rowred[row_l], u);
        }
    }
#pragma unroll
    for (int ni = 0; ni < 4; ni++) {
#pragma unroll
        for (int c = 0; c < 2; c++) {
            float v = cmin[ni][c];
#pragma unroll
            for (int off = 4; off <= 16; off <<= 1)
                v = fminf(v, __shfl_xor_sync(0xFFFFFFFFu, v, off));
            if (qr == 0) {
                int col_l = wn * 32 + ni * 8 + 2 * qc + c;
                atomicMin(&colred[col_l], __float_as_uint(v));
            }
        }
    }
    __syncthreads();
    if (tid < 128) {
        atomicMin(&g_rowbest[m0 + tid], rowred[tid]);
        atomicMin(&g_colmin[c0 + tid], colred[tid]);
    }
}

// ---------------------------------------------------------------------------
// Kernel 3: gather emb, write out = x + (emb - x), partial SSE per block
// ---------------------------------------------------------------------------
__global__ void vq_gather(const float* __restrict__ x, const float* __restrict__ cb,
                          float* __restrict__ out) {
    int row = blockIdx.x * blockDim.x + threadIdx.x;
    int tok = (int)(unsigned int)(g_rowbest[row] & 0xFFFFFFFFull);
    const float4* xg = reinterpret_cast<const float4*>(x) + (size_t)row * 16;
    const float4* cg = reinterpret_cast<const float4*>(cb) + (size_t)tok * 16;
    float4* og = reinterpret_cast<float4*>(out) + (size_t)row * 16;
    float s = 0.f;
#pragma unroll
    for (int i = 0; i < 16; i++) {
        float4 xv = xg[i];
        float4 e = cg[i];
        float dx = e.x - xv.x, dy = e.y - xv.y, dz = e.z - xv.z, dw = e.w - xv.w;
        s += dx * dx + dy * dy + dz * dz + dw * dw;
        og[i] = make_float4(xv.x + dx, xv.y + dy, xv.z + dz, xv.w + dw);
    }
#pragma unroll
    for (int off = 16; off; off >>= 1) s += __shfl_xor_sync(0xFFFFFFFFu, s, off);
    __shared__ float red[8];
    int lane = threadIdx.x & 31, wid = threadIdx.x >> 5;
    if (lane == 0) red[wid] = s;
    __syncthreads();
    if (threadIdx.x == 0) {
        float t = 0.f;
#pragma unroll
        for (int i = 0; i < 8; i++) t += red[i];
        g_partials[blockIdx.x] = t;
    }
}

// ---------------------------------------------------------------------------
// Kernel 4: finalize loss scalar
// ---------------------------------------------------------------------------
__global__ void vq_final(float* __restrict__ out, int nd, int out_size) {
    int t = threadIdx.x;  // 256 threads
    float s = (t < (N_ROWS / 256)) ? g_partials[t] : 0.f;
    float cm = 0.f;
#pragma unroll
    for (int i = 0; i < KCODES / 256; i++)
        cm += __uint_as_float(g_colmin[t + i * 256]);
#pragma unroll
    for (int off = 16; off; off >>= 1) {
        s += __shfl_xor_sync(0xFFFFFFFFu, s, off);
        cm += __shfl_xor_sync(0xFFFFFFFFu, cm, off);
    }
    __shared__ float sh_s[8], sh_c[8];
    int lane = t & 31, wid = t >> 5;
    if (lane == 0) { sh_s[wid] = s; sh_c[wid] = cm; }
    __syncthreads();
    if (t == 0) {
        float st = 0.f, ct = 0.f;
#pragma unroll
        for (int i = 0; i < 8; i++) { st += sh_s[i]; ct += sh_c[i]; }
        float loss = 1.25f * (st / (float)nd) + 0.1f * (ct * (1.f / (float)KCODES));
        for (int i = nd; i < out_size; i++) out[i] = loss;
    }
}

// ---------------------------------------------------------------------------
extern "C" void kernel_launch(void* const* d_in, const int* in_sizes, int n_in,
                              void* d_out, int out_size) {
    const float* x = (const float*)d_in[0];   // [32,32,32,64] fp32
    const float* cb = (const float*)d_in[1];  // [1024,64] fp32
    float* out = (float*)d_out;
    int nd = in_sizes[0];  // 2097152

    cudaFuncSetAttribute(vq_main_mma, cudaFuncAttributeMaxDynamicSharedMemorySize,
                         SMEM_SZ);

    vq_prep<<<64, 512>>>(x, cb);
    vq_split_x<<<(N_ROWS * 16) / 256, 256>>>(x);
    vq_split_c<<<(KCODES * 16) / 256, 256>>>(cb);
    dim3 grid(N_ROWS / M_TILE, KCODES / N_TILE);  // (256, 8)
    vq_main_mma<<<grid, 256, SMEM_SZ>>>();
    vq_gather<<<N_ROWS / 256, 256>>>(x, cb, out);
    vq_final<<<1, 256>>>(out, nd, out_size);
}

// round 10
// speedup vs baseline: 1.5965x; 1.0004x over previous
#include <cuda_runtime.h>
#include <cuda_fp16.h>
#include <cstdint>

// Problem constants (B,H,W,D = 32,32,32,64; K = 1024)
#define N_ROWS 32768
#define DIM    64
#define KCODES 1024
#define M_TILE 128
#define N_TILE 128
#define KAUG   192              // 3 chunks x 64 (fp16 2-level split, 3 product terms)
#define KSTEPS (KAUG / 16)      // 12

// ---------------------------------------------------------------------------
// Device scratch (no allocation allowed)
// ---------------------------------------------------------------------------
__device__ unsigned long long g_rowbest[N_ROWS];   // (dist_bits<<32)|code
__device__ unsigned int       g_colmin[KCODES];    // per-code min dist (float bits)
__device__ float              g_xnorm[N_ROWS];
__device__ float              g_cnorm[KCODES];
__device__ float              g_partials[N_ROWS / 256];
__device__ unsigned int       g_done;
__device__ __align__(16) __half g_xaug[(size_t)N_ROWS * KAUG];  // 12.6 MB
__device__ __align__(16) __half g_caug[(size_t)KCODES * KAUG];  // 384 KB

// ---------------------------------------------------------------------------
// SMEM layout (dynamic). Padded K-stride: 192 halfs -> 200 halfs = 400 B
// (rows land on distinct 4-bank groups => conflict-free ldmatrix).
// ---------------------------------------------------------------------------
#define ROWB      400
#define SO_CN     0                        // 128 floats
#define SO_XN     512                      // 128 floats
#define SO_ROWRED 1024                     // 128 u64
#define SO_COLRED 2048                     // 128 u32
#define SO_A      2560                     // 128 * 400 B = 51200
#define SO_B      (SO_A + M_TILE * ROWB)   // 53760
#define SMEM_SZ   (SO_B + N_TILE * ROWB)   // 104960 B

__device__ __forceinline__ uint32_t smem_to_u32(const void* p) {
    uint32_t a;
    asm("{ .reg .u64 t; cvta.to.shared.u64 t, %1; cvt.u32.u64 %0, t; }"
        : "=r"(a) : "l"(p));
    return a;
}

#define LDSM_X4(r0, r1, r2, r3, addr) \
    asm volatile("ldmatrix.sync.aligned.m8n8.x4.shared.b16 {%0,%1,%2,%3}, [%4];" \
                 : "=r"(r0), "=r"(r1), "=r"(r2), "=r"(r3) : "r"(addr))

#define MMA16816(c, a0, a1, a2, a3, b0, b1) \
    asm volatile( \
        "mma.sync.aligned.m16n8k16.row.col.f32.f16.f16.f32 " \
        "{%0,%1,%2,%3}, {%4,%5,%6,%7}, {%8,%9}, {%0,%1,%2,%3};" \
        : "+f"((c)[0]), "+f"((c)[1]), "+f"((c)[2]), "+f"((c)[3]) \
        : "r"(a0), "r"(a1), "r"(a2), "r"(a3), "r"(b0), "r"(b1))

#define CP_ASYNC16(dst, src) \
    asm volatile("cp.async.ca.shared.global [%0], [%1], 16;" \
                 :: "r"((uint32_t)(dst)), "l"(src))
#define CP_ASYNC_COMMIT() asm volatile("cp.async.commit_group;" ::: "memory")
#define CP_ASYNC_WAIT0()  asm volatile("cp.async.wait_group 0;" ::: "memory")

// ---------------------------------------------------------------------------
// fp16 2-level split, 3 product terms:
//   X chunks: [hi, hi, mid]   C chunks: [hi, mid, hi]
//   sum = hi_x*hi_c + hi_x*mid_c + mid_x*hi_c  (drop mid*mid ~ 2^-22)
// ---------------------------------------------------------------------------
__device__ __forceinline__ void split2h(float v, __half& h, __half& m) {
    h = __float2half_rn(v);
    m = __float2half_rn(v - __half2float(h));
}
__device__ __forceinline__ uint32_t hpack(__half a, __half b) {
    __half2 t = __halves2half2(a, b);
    return *reinterpret_cast<uint32_t*>(&t);
}

// ---------------------------------------------------------------------------
// Kernel 1 (fused): norms + scratch init + fp16 split for x and codebook.
// One thread per row; rows [0, N_ROWS) = x, rows [N_ROWS, N_ROWS+KCODES) = cb.
// ---------------------------------------------------------------------------
__global__ void vq_prep_split(const float* __restrict__ x,
                              const float* __restrict__ cb) {
    int t = blockIdx.x * blockDim.x + threadIdx.x;  // 33792 threads
    if (t == 0) g_done = 0;
    const bool isx = t < N_ROWS;
    const int row = isx ? t : t - N_ROWS;
    const float4* p = reinterpret_cast<const float4*>(isx ? x : cb) +
                      (size_t)row * (DIM / 4);
    __half* aug = isx ? g_xaug : g_caug;
    float s = 0.f;
#pragma unroll
    for (int q = 0; q < 16; q++) {
        float4 v = p[q];
        s += v.x * v.x + v.y * v.y + v.z * v.z + v.w * v.w;
        __half h[4], m[4];
        split2h(v.x, h[0], m[0]);
        split2h(v.y, h[1], m[1]);
        split2h(v.z, h[2], m[2]);
        split2h(v.w, h[3], m[3]);
        uint2 hh = make_uint2(hpack(h[0], h[1]), hpack(h[2], h[3]));
        uint2 mm = make_uint2(hpack(m[0], m[1]), hpack(m[2], m[3]));
        size_t base = (size_t)row * KAUG + q * 4;
        if (isx) {
            *reinterpret_cast<uint2*>(&aug[base + 0 * 64]) = hh;
            *reinterpret_cast<uint2*>(&aug[base + 1 * 64]) = hh;
            *reinterpret_cast<uint2*>(&aug[base + 2 * 64]) = mm;
        } else {
            *reinterpret_cast<uint2*>(&aug[base + 0 * 64]) = hh;
            *reinterpret_cast<uint2*>(&aug[base + 1 * 64]) = mm;
            *reinterpret_cast<uint2*>(&aug[base + 2 * 64]) = hh;
        }
    }
    if (isx) {
        g_xnorm[row] = s;
        g_rowbest[row] = 0xFFFFFFFFFFFFFFFFull;
    } else {
        g_cnorm[row] = s;
        g_colmin[row] = 0x7F800000u;
    }
}

// ---------------------------------------------------------------------------
// Kernel 2: mma.sync HMMA GEMM tile (128x128, K=192) + argmin/colmin epilogue
// 8 warps in a 2x4 grid; warp tile 64x32; cp.async staging; fragment
// double-buffering (prefetch k-step ks+1 during the 16 MMAs of ks).
// ---------------------------------------------------------------------------
__global__ void __launch_bounds__(256, 2) vq_main_mma() {
    extern __shared__ char smem[];
    uint32_t sb = smem_to_u32(smem);
    float* cn_s = reinterpret_cast<float*>(smem + SO_CN);
    float* xn_s = reinterpret_cast<float*>(smem + SO_XN);
    unsigned long long* rowred =
        reinterpret_cast<unsigned long long*>(smem + SO_ROWRED);
    unsigned int* colred = reinterpret_cast<unsigned int*>(smem + SO_COLRED);

    const int tid = threadIdx.x;
    const int wid = tid >> 5, lane = tid & 31;
    const int wm = wid & 1;       // m block of 64
    const int wn = wid >> 1;      // n block of 32
    const int m0 = blockIdx.x * M_TILE;
    const int c0 = blockIdx.y * N_TILE;

    // Stage A (128 x 192 halfs) and B (128 x 192 halfs) via cp.async.
    const uint4* xa = reinterpret_cast<const uint4*>(g_xaug);  // 24 uint4 / row
    const uint4* ca = reinterpret_cast<const uint4*>(g_caug);
#pragma unroll
    for (int i = 0; i < 12; i++) {
        int idx = tid + i * 256;            // 0..3071
        int r = idx / 24, q = idx - r * 24;
        CP_ASYNC16(sb + SO_A + r * ROWB + q * 16, &xa[(size_t)(m0 + r) * 24 + q]);
        CP_ASYNC16(sb + SO_B + r * ROWB + q * 16, &ca[(size_t)(c0 + r) * 24 + q]);
    }
    CP_ASYNC_COMMIT();

    if (tid < 128) {
        cn_s[tid] = g_cnorm[c0 + tid];
        xn_s[tid] = g_xnorm[m0 + tid];
        rowred[tid] = 0xFFFFFFFFFFFFFFFFull;
        colred[tid] = 0x7F800000u;
    }
    CP_ASYNC_WAIT0();
    __syncthreads();

    // ldmatrix base addresses
    // A x4: lanes 0-15 -> rows (lane&15) @k0, lanes 16-31 -> same rows @k+8
    uint32_t a_base = sb + SO_A + (wm * 64 + (lane & 15)) * ROWB + (lane >> 4) * 16;
    // B x4 (two n-subtiles): group g = lane>>3:
    //   g0: n0-7 @k0, g1: n0-7 @k8, g2: n8-15 @k0, g3: n8-15 @k8
    const int bg = lane >> 3;
    const int bn = ((bg >> 1) << 3) + (lane & 7);   // 0..15 within 16-n pair
    const int bk = (bg & 1) * 16;                   // byte offset (8 halfs)
    uint32_t b_base0 = sb + SO_B + (wn * 32 + 0 + bn) * ROWB + bk;
    uint32_t b_base1 = sb + SO_B + (wn * 32 + 16 + bn) * ROWB + bk;

    float acc[4][4][4];
#pragma unroll
    for (int mi = 0; mi < 4; mi++)
#pragma unroll
        for (int ni = 0; ni < 4; ni++)
#pragma unroll
            for (int j = 0; j < 4; j++) acc[mi][ni][j] = 0.f;

    // Double-buffered fragments
    uint32_t afr[2][4][4], bfr[2][2][4];
#pragma unroll
    for (int mi = 0; mi < 4; mi++)
        LDSM_X4(afr[0][mi][0], afr[0][mi][1], afr[0][mi][2], afr[0][mi][3],
                a_base + mi * 16 * ROWB);
    LDSM_X4(bfr[0][0][0], bfr[0][0][1], bfr[0][0][2], bfr[0][0][3], b_base0);
    LDSM_X4(bfr[0][1][0], bfr[0][1][1], bfr[0][1][2], bfr[0][1][3], b_base1);

#pragma unroll
    for (int ks = 0; ks < KSTEPS; ks++) {
        const int cur = ks & 1, nxt = cur ^ 1;
        if (ks < KSTEPS - 1) {
#pragma unroll
            for (int mi = 0; mi < 4; mi++)
                LDSM_X4(afr[nxt][mi][0], afr[nxt][mi][1], afr[nxt][mi][2],
                        afr[nxt][mi][3],
                        a_base + mi * 16 * ROWB + (ks + 1) * 32);
            LDSM_X4(bfr[nxt][0][0], bfr[nxt][0][1], bfr[nxt][0][2],
                    bfr[nxt][0][3], b_base0 + (ks + 1) * 32);
            LDSM_X4(bfr[nxt][1][0], bfr[nxt][1][1], bfr[nxt][1][2],
                    bfr[nxt][1][3], b_base1 + (ks + 1) * 32);
        }
#pragma unroll
        for (int mi = 0; mi < 4; mi++) {
#pragma unroll
            for (int ni = 0; ni < 4; ni++) {
                const int p = ni >> 1, o = (ni & 1) * 2;
                MMA16816(acc[mi][ni], afr[cur][mi][0], afr[cur][mi][1],
                         afr[cur][mi][2], afr[cur][mi][3],
                         bfr[cur][p][o], bfr[cur][p][o + 1]);
            }
        }
    }

    // ---------------- Epilogue ----------------
    const int qr = lane >> 2, qc = lane & 3;
    const float INF = __int_as_float(0x7f800000);
    float cmin[4][2];
#pragma unroll
    for (int ni = 0; ni < 4; ni++) { cmin[ni][0] = INF; cmin[ni][1] = INF; }

#pragma unroll
    for (int mi = 0; mi < 4; mi++) {
#pragma unroll
        for (int h = 0; h < 2; h++) {
            int row_l = wm * 64 + mi * 16 + qr + 8 * h;
            float xn = xn_s[row_l];
            float bd = INF;
            int bc = 0;
#pragma unroll
            for (int ni = 0; ni < 4; ni++) {
#pragma unroll
                for (int c = 0; c < 2; c++) {
                    int col_l = wn * 32 + ni * 8 + 2 * qc + c;
                    float d = fmaf(-2.f, acc[mi][ni][2 * h + c], xn + cn_s[col_l]);
                    if (d < bd) { bd = d; bc = col_l; }
                    cmin[ni][c] = fminf(cmin[ni][c], d);
                }
            }
            unsigned long long u =
                ((unsigned long long)__float_as_uint(bd) << 32) |
                (unsigned int)(c0 + bc);
#pragma unroll
            for (int off = 1; off <= 2; off <<= 1) {
                unsigned long long o = __shfl_xor_sync(0xFFFFFFFFu, u, off);
                if (o < u) u = o;
            }
            if (qc == 0) atomicMin(&rowred[row_l], u);
        }
    }
#pragma unroll
    for (int ni = 0; ni < 4; ni++) {
#pragma unroll
        for (int c = 0; c < 2; c++) {
            float v = cmin[ni][c];
#pragma unroll
            for (int off = 4; off <= 16; off <<= 1)
                v = fminf(v, __shfl_xor_sync(0xFFFFFFFFu, v, off));
            if (qr == 0) {
                int col_l = wn * 32 + ni * 8 + 2 * qc + c;
                atomicMin(&colred[col_l], __float_as_uint(v));
            }
        }
    }
    __syncthreads();
    if (tid < 128) {
        atomicMin(&g_rowbest[m0 + tid], rowred[tid]);
        atomicMin(&g_colmin[c0 + tid], colred[tid]);
    }
}

// ---------------------------------------------------------------------------
// Kernel 3 (fused): gather emb, write out = x + (emb-x), partial SSE;
// last block finalizes the loss scalar (deterministic fixed-order sums).
// ---------------------------------------------------------------------------
__global__ void vq_gather_final(const float* __restrict__ x,
                                const float* __restrict__ cb,
                                float* __restrict__ out, int nd, int out_size) {
    int row = blockIdx.x * blockDim.x + threadIdx.x;
    int tok = (int)(unsigned int)(g_rowbest[row] & 0xFFFFFFFFull);
    const float4* xg = reinterpret_cast<const float4*>(x) + (size_t)row * 16;
    const float4* cg = reinterpret_cast<const float4*>(cb) + (size_t)tok * 16;
    float4* og = reinterpret_cast<float4*>(out) + (size_t)row * 16;
    float s = 0.f;
#pragma unroll
    for (int i = 0; i < 16; i++) {
        float4 xv = xg[i];
        float4 e = cg[i];
        float dx = e.x - xv.x, dy = e.y - xv.y, dz = e.z - xv.z, dw = e.w - xv.w;
        s += dx * dx + dy * dy + dz * dz + dw * dw;
        og[i] = make_float4(xv.x + dx, xv.y + dy, xv.z + dz, xv.w + dw);
    }
#pragma unroll
    for (int off = 16; off; off >>= 1) s += __shfl_xor_sync(0xFFFFFFFFu, s, off);
    __shared__ float red[8];
    __shared__ unsigned int ticket;
    int lane = threadIdx.x & 31, wid = threadIdx.x >> 5;
    if (lane == 0) red[wid] = s;
    __syncthreads();
    if (threadIdx.x == 0) {
        float t = 0.f;
#pragma unroll
        for (int i = 0; i < 8; i++) t += red[i];
        g_partials[blockIdx.x] = t;
        __threadfence();
        ticket = atomicAdd(&g_done, 1u);
    }
    __syncthreads();
    if (ticket != gridDim.x - 1) return;

    // Last block: finalize the loss (256 threads)
    int t = threadIdx.x;
    float ps = (t < (N_ROWS / 256)) ? g_partials[t] : 0.f;
    float cm = 0.f;
#pragma unroll
    for (int i = 0; i < KCODES / 256; i++)
        cm += __uint_as_float(g_colmin[t + i * 256]);
#pragma unroll
    for (int off = 16; off; off >>= 1) {
        ps += __shfl_xor_sync(0xFFFFFFFFu, ps, off);
        cm += __shfl_xor_sync(0xFFFFFFFFu, cm, off);
    }
    __shared__ float sh_s[8], sh_c[8];
    if (lane == 0) { sh_s[wid] = ps; sh_c[wid] = cm; }
    __syncthreads();
    if (t == 0) {
        float st = 0.f, ct = 0.f;
#pragma unroll
        for (int i = 0; i < 8; i++) { st += sh_s[i]; ct += sh_c[i]; }
        float loss = 1.25f * (st / (float)nd) + 0.1f * (ct * (1.f / (float)KCODES));
        for (int i = nd; i < out_size; i++) out[i] = loss;
    }
}

// ---------------------------------------------------------------------------
extern "C" void kernel_launch(void* const* d_in, const int* in_sizes, int n_in,
                              void* d_out, int out_size) {
    const float* x = (const float*)d_in[0];   // [32,32,32,64] fp32
    const float* cb = (const float*)d_in[1];  // [1024,64] fp32
    float* out = (float*)d_out;
    int nd = in_sizes[0];  // 2097152

    cudaFuncSetAttribute(vq_main_mma, cudaFuncAttributeMaxDynamicSharedMemorySize,
                         SMEM_SZ);

    vq_prep_split<<<(N_ROWS + KCODES) / 256, 256>>>(x, cb);
    dim3 grid(N_ROWS / M_TILE, KCODES / N_TILE);  // (256, 8)
    vq_main_mma<<<grid, 256, SMEM_SZ>>>();
    vq_gather_final<<<N_ROWS / 256, 256>>>(x, cb, out, nd, out_size);
}

// round 13
// speedup vs baseline: 1.9095x; 1.1960x over previous
#include <cuda_runtime.h>
#include <cuda_fp16.h>
#include <cstdint>

// Problem constants (B,H,W,D = 32,32,32,64; K = 1024)
#define N_ROWS 32768
#define DIM    64
#define KCODES 1024
#define M_TILE 128
#define N_TILE 128
#define KAUG   192              // 3 chunks x 64 (fp16 2-level split, 3 product terms)
#define KSTEPS (KAUG / 16)      // 12
#define NT     512              // threads per CTA in main kernel (16 warps, 4x4)

// ---------------------------------------------------------------------------
// Device scratch (no allocation allowed)
// ---------------------------------------------------------------------------
__device__ unsigned long long g_rowbest[N_ROWS];   // (dist_bits<<32)|code
__device__ unsigned int       g_colmin[KCODES];    // per-code min dist (float bits)
__device__ float              g_xnorm[N_ROWS];
__device__ float              g_cnorm[KCODES];
__device__ float              g_partials[N_ROWS / 256];
__device__ unsigned int       g_done;
__device__ __align__(16) __half g_xaug[(size_t)N_ROWS * KAUG];  // 12.6 MB
__device__ __align__(16) __half g_caug[(size_t)KCODES * KAUG];  // 384 KB

// ---------------------------------------------------------------------------
// SMEM layout (dynamic). Padded K-stride: 192 halfs -> 200 halfs = 400 B
// (rows land on distinct 4-bank groups => conflict-free ldmatrix).
// ---------------------------------------------------------------------------
#define ROWB      400
#define SO_CN     0                        // 128 floats
#define SO_XN     512                      // 128 floats
#define SO_ROWRED 1024                     // 128 u64
#define SO_COLRED 2048                     // 128 u32
#define SO_A      2560                     // 128 * 400 B = 51200
#define SO_B      (SO_A + M_TILE * ROWB)   // 53760
#define SMEM_SZ   (SO_B + N_TILE * ROWB)   // 104960 B

__device__ __forceinline__ uint32_t smem_to_u32(const void* p) {
    uint32_t a;
    asm("{ .reg .u64 t; cvta.to.shared.u64 t, %1; cvt.u32.u64 %0, t; }"
        : "=r"(a) : "l"(p));
    return a;
}

#define LDSM_X4(r0, r1, r2, r3, addr) \
    asm volatile("ldmatrix.sync.aligned.m8n8.x4.shared.b16 {%0,%1,%2,%3}, [%4];" \
                 : "=r"(r0), "=r"(r1), "=r"(r2), "=r"(r3) : "r"(addr))

#define MMA16816(c, a0, a1, a2, a3, b0, b1) \
    asm volatile( \
        "mma.sync.aligned.m16n8k16.row.col.f32.f16.f16.f32 " \
        "{%0,%1,%2,%3}, {%4,%5,%6,%7}, {%8,%9}, {%0,%1,%2,%3};" \
        : "+f"((c)[0]), "+f"((c)[1]), "+f"((c)[2]), "+f"((c)[3]) \
        : "r"(a0), "r"(a1), "r"(a2), "r"(a3), "r"(b0), "r"(b1))

#define CP_ASYNC16(dst, src) \
    asm volatile("cp.async.ca.shared.global [%0], [%1], 16;" \
                 :: "r"((uint32_t)(dst)), "l"(src))
#define CP_ASYNC_COMMIT() asm volatile("cp.async.commit_group;" ::: "memory")
#define CP_ASYNC_WAIT0()  asm volatile("cp.async.wait_group 0;" ::: "memory")

// ---------------------------------------------------------------------------
// fp16 2-level split, 3 product terms:
//   X chunks: [hi, hi, mid]   C chunks: [hi, mid, hi]
//   sum = hi_x*hi_c + hi_x*mid_c + mid_x*hi_c  (drop mid*mid ~ 2^-22)
// ---------------------------------------------------------------------------
__device__ __forceinline__ void split2h(float v, __half& h, __half& m) {
    h = __float2half_rn(v);
    m = __float2half_rn(v - __half2float(h));
}
__device__ __forceinline__ uint32_t hpack(__half a, __half b) {
    __half2 t = __halves2half2(a, b);
    return *reinterpret_cast<uint32_t*>(&t);
}

// ---------------------------------------------------------------------------
// Kernel 1: norms + scratch init + fp16 split. 16 threads per row (one per
// float4 quad), coalesced reads and chunk writes, 16-lane shuffle for norms.
// ---------------------------------------------------------------------------
__global__ void vq_prep_split(const float* __restrict__ x,
                              const float* __restrict__ cb) {
    int t = blockIdx.x * blockDim.x + threadIdx.x;  // (N_ROWS+KCODES)*16 threads
    if (t == 0) g_done = 0;
    int rowg = t >> 4, q = t & 15;
    const bool isx = rowg < N_ROWS;
    const int row = isx ? rowg : rowg - N_ROWS;
    float4 v = reinterpret_cast<const float4*>(isx ? x : cb)[(size_t)row * 16 + q];

    float s = v.x * v.x + v.y * v.y + v.z * v.z + v.w * v.w;
#pragma unroll
    for (int off = 1; off <= 8; off <<= 1)
        s += __shfl_xor_sync(0xFFFFFFFFu, s, off);

    __half h[4], m[4];
    split2h(v.x, h[0], m[0]);
    split2h(v.y, h[1], m[1]);
    split2h(v.z, h[2], m[2]);
    split2h(v.w, h[3], m[3]);
    uint2 hh = make_uint2(hpack(h[0], h[1]), hpack(h[2], h[3]));
    uint2 mm = make_uint2(hpack(m[0], m[1]), hpack(m[2], m[3]));
    size_t base = (size_t)row * KAUG + q * 4;
    if (isx) {
        *reinterpret_cast<uint2*>(&g_xaug[base + 0 * 64]) = hh;
        *reinterpret_cast<uint2*>(&g_xaug[base + 1 * 64]) = hh;
        *reinterpret_cast<uint2*>(&g_xaug[base + 2 * 64]) = mm;
        if (q == 0) {
            g_xnorm[row] = s;
            g_rowbest[row] = 0xFFFFFFFFFFFFFFFFull;
        }
    } else {
        *reinterpret_cast<uint2*>(&g_caug[base + 0 * 64]) = hh;
        *reinterpret_cast<uint2*>(&g_caug[base + 1 * 64]) = mm;
        *reinterpret_cast<uint2*>(&g_caug[base + 2 * 64]) = hh;
        if (q == 0) {
            g_cnorm[row] = s;
            g_colmin[row] = 0x7F800000u;
        }
    }
}

// ---------------------------------------------------------------------------
// Kernel 2: mma.sync HMMA GEMM tile (128x128, K=192) + argmin/colmin epilogue
// 16 warps in a 4x4 grid; warp tile 32x32; cp.async staging.
// ---------------------------------------------------------------------------
__global__ void __launch_bounds__(NT, 2) vq_main_mma() {
    extern __shared__ char smem[];
    uint32_t sb = smem_to_u32(smem);
    float* cn_s = reinterpret_cast<float*>(smem + SO_CN);
    float* xn_s = reinterpret_cast<float*>(smem + SO_XN);
    unsigned long long* rowred =
        reinterpret_cast<unsigned long long*>(smem + SO_ROWRED);
    unsigned int* colred = reinterpret_cast<unsigned int*>(smem + SO_COLRED);

    const int tid = threadIdx.x;
    const int wid = tid >> 5, lane = tid & 31;
    const int wm = wid & 3;       // m block of 32
    const int wn = wid >> 2;      // n block of 32
    const int m0 = blockIdx.x * M_TILE;
    const int c0 = blockIdx.y * N_TILE;

    // Stage A and B tiles (128 x 192 halfs each) via cp.async.
    const uint4* xa = reinterpret_cast<const uint4*>(g_xaug);  // 24 uint4 / row
    const uint4* ca = reinterpret_cast<const uint4*>(g_caug);
#pragma unroll
    for (int i = 0; i < 6; i++) {
        int idx = tid + i * NT;             // 0..3071
        int r = idx / 24, q = idx - r * 24;
        CP_ASYNC16(sb + SO_A + r * ROWB + q * 16, &xa[(size_t)(m0 + r) * 24 + q]);
        CP_ASYNC16(sb + SO_B + r * ROWB + q * 16, &ca[(size_t)(c0 + r) * 24 + q]);
    }
    CP_ASYNC_COMMIT();

    if (tid < 128) {
        cn_s[tid] = g_cnorm[c0 + tid];
        xn_s[tid] = g_xnorm[m0 + tid];
        rowred[tid] = 0xFFFFFFFFFFFFFFFFull;
        colred[tid] = 0x7F800000u;
    }
    CP_ASYNC_WAIT0();
    __syncthreads();

    // ldmatrix bases
    // A x4: lanes 0-15 -> rows (lane&15) @k0, lanes 16-31 -> same rows @k+8
    uint32_t a_base = sb + SO_A + (wm * 32 + (lane & 15)) * ROWB + (lane >> 4) * 16;
    // B x4: group g = lane>>3: g0 n0-7@k0, g1 n0-7@k8, g2 n8-15@k0, g3 n8-15@k8
    const int bg = lane >> 3;
    const int bn = ((bg >> 1) << 3) + (lane & 7);
    const int bk = (bg & 1) * 16;
    uint32_t b_base0 = sb + SO_B + (wn * 32 + 0 + bn) * ROWB + bk;
    uint32_t b_base1 = sb + SO_B + (wn * 32 + 16 + bn) * ROWB + bk;

    float acc[2][4][4];
#pragma unroll
    for (int mi = 0; mi < 2; mi++)
#pragma unroll
        for (int ni = 0; ni < 4; ni++)
#pragma unroll
            for (int j = 0; j < 4; j++) acc[mi][ni][j] = 0.f;

#pragma unroll
    for (int ks = 0; ks < KSTEPS; ks++) {
        uint32_t a[2][4], b[2][4];
#pragma unroll
        for (int mi = 0; mi < 2; mi++)
            LDSM_X4(a[mi][0], a[mi][1], a[mi][2], a[mi][3],
                    a_base + mi * 16 * ROWB + ks * 32);
        LDSM_X4(b[0][0], b[0][1], b[0][2], b[0][3], b_base0 + ks * 32);
        LDSM_X4(b[1][0], b[1][1], b[1][2], b[1][3], b_base1 + ks * 32);
#pragma unroll
        for (int mi = 0; mi < 2; mi++) {
#pragma unroll
            for (int ni = 0; ni < 4; ni++) {
                const int p = ni >> 1, o = (ni & 1) * 2;
                MMA16816(acc[mi][ni], a[mi][0], a[mi][1], a[mi][2], a[mi][3],
                         b[p][o], b[p][o + 1]);
            }
        }
    }

    // ---------------- Epilogue ----------------
    const int qr = lane >> 2, qc = lane & 3;
    const float INF = __int_as_float(0x7f800000);
    float cmin[4][2];
#pragma unroll
    for (int ni = 0; ni < 4; ni++) { cmin[ni][0] = INF; cmin[ni][1] = INF; }

#pragma unroll
    for (int mi = 0; mi < 2; mi++) {
#pragma unroll
        for (int h = 0; h < 2; h++) {
            int row_l = wm * 32 + mi * 16 + qr + 8 * h;
            float xn = xn_s[row_l];
            float bd = INF;
            int bc = 0;
#pragma unroll
            for (int ni = 0; ni < 4; ni++) {
#pragma unroll
                for (int c = 0; c < 2; c++) {
                    int col_l = wn * 32 + ni * 8 + 2 * qc + c;
                    float d = fmaf(-2.f, acc[mi][ni][2 * h + c], xn + cn_s[col_l]);
                    if (d < bd) { bd = d; bc = col_l; }
                    cmin[ni][c] = fminf(cmin[ni][c], d);
                }
            }
            unsigned long long u =
                ((unsigned long long)__float_as_uint(bd) << 32) |
                (unsigned int)(c0 + bc);
#pragma unroll
            for (int off = 1; off <= 2; off <<= 1) {
                unsigned long long o = __shfl_xor_sync(0xFFFFFFFFu, u, off);
                if (o < u) u = o;
            }
            if (qc == 0) atomicMin(&rowred[row_l], u);
        }
    }
#pragma unroll
    for (int ni = 0; ni < 4; ni++) {
#pragma unroll
        for (int c = 0; c < 2; c++) {
            float v = cmin[ni][c];
#pragma unroll
            for (int off = 4; off <= 16; off <<= 1)
                v = fminf(v, __shfl_xor_sync(0xFFFFFFFFu, v, off));
            if (qr == 0) {
                int col_l = wn * 32 + ni * 8 + 2 * qc + c;
                atomicMin(&colred[col_l], __float_as_uint(v));
            }
        }
    }
    __syncthreads();
    if (tid < 128) {
        atomicMin(&g_rowbest[m0 + tid], rowred[tid]);
        atomicMin(&g_colmin[c0 + tid], colred[tid]);
    }
}

// ---------------------------------------------------------------------------
// Kernel 3 (fused): gather emb, write out = x + (emb-x), partial SSE;
// last block finalizes the loss scalar (deterministic fixed-order sums).
// ---------------------------------------------------------------------------
__global__ void vq_gather_final(const float* __restrict__ x,
                                const float* __restrict__ cb,
                                float* __restrict__ out, int nd, int out_size) {
    int row = blockIdx.x * blockDim.x + threadIdx.x;
    int tok = (int)(unsigned int)(g_rowbest[row] & 0xFFFFFFFFull);
    const float4* xg = reinterpret_cast<const float4*>(x) + (size_t)row * 16;
    const float4* cg = reinterpret_cast<const float4*>(cb) + (size_t)tok * 16;
    float4* og = reinterpret_cast<float4*>(out) + (size_t)row * 16;
    float s = 0.f;
#pragma unroll
    for (int i = 0; i < 16; i++) {
        float4 xv = xg[i];
        float4 e = cg[i];
        float dx = e.x - xv.x, dy = e.y - xv.y, dz = e.z - xv.z, dw = e.w - xv.w;
        s += dx * dx + dy * dy + dz * dz + dw * dw;
        og[i] = make_float4(xv.x + dx, xv.y + dy, xv.z + dz, xv.w + dw);
    }
#pragma unroll
    for (int off = 16; off; off >>= 1) s += __shfl_xor_sync(0xFFFFFFFFu, s, off);
    __shared__ float red[8];
    __shared__ unsigned int ticket;
    int lane = threadIdx.x & 31, wid = threadIdx.x >> 5;
    if (lane == 0) red[wid] = s;
    __syncthreads();
    if (threadIdx.x == 0) {
        float t = 0.f;
#pragma unroll
        for (int i = 0; i < 8; i++) t += red[i];
        g_partials[blockIdx.x] = t;
        __threadfence();
        ticket = atomicAdd(&g_done, 1u);
    }
    __syncthreads();
    if (ticket != gridDim.x - 1) return;

    // Last block: finalize the loss (256 threads)
    int t = threadIdx.x;
    float ps = (t < (N_ROWS / 256)) ? g_partials[t] : 0.f;
    float cm = 0.f;
#pragma unroll
    for (int i = 0; i < KCODES / 256; i++)
        cm += __uint_as_float(g_colmin[t + i * 256]);
#pragma unroll
    for (int off = 16; off; off >>= 1) {
        ps += __shfl_xor_sync(0xFFFFFFFFu, ps, off);
        cm += __shfl_xor_sync(0xFFFFFFFFu, cm, off);
    }
    __shared__ float sh_s[8], sh_c[8];
    if (lane == 0) { sh_s[wid] = ps; sh_c[wid] = cm; }
    __syncthreads();
    if (t == 0) {
        float st = 0.f, ct = 0.f;
#pragma unroll
        for (int i = 0; i < 8; i++) { st += sh_s[i]; ct += sh_c[i]; }
        float loss = 1.25f * (st / (float)nd) + 0.1f * (ct * (1.f / (float)KCODES));
        for (int i = nd; i < out_size; i++) out[i] = loss;
    }
}

// ---------------------------------------------------------------------------
extern "C" void kernel_launch(void* const* d_in, const int* in_sizes, int n_in,
                              void* d_out, int out_size) {
    const float* x = (const float*)d_in[0];   // [32,32,32,64] fp32
    const float* cb = (const float*)d_in[1];  // [1024,64] fp32
    float* out = (float*)d_out;
    int nd = in_sizes[0];  // 2097152

    cudaFuncSetAttribute(vq_main_mma, cudaFuncAttributeMaxDynamicSharedMemorySize,
                         SMEM_SZ);

    vq_prep_split<<<((N_ROWS + KCODES) * 16) / 256, 256>>>(x, cb);
    dim3 grid(N_ROWS / M_TILE, KCODES / N_TILE);  // (256, 8)
    vq_main_mma<<<grid, NT, SMEM_SZ>>>();
    vq_gather_final<<<N_ROWS / 256, 256>>>(x, cb, out, nd, out_size);
}